// round 12
// baseline (speedup 1.0000x reference)
#include <cuda_runtime.h>
#include <cstdint>

// Exact spike counter (reset each launch by zero_cnt so graph replay is
// deterministic). unsigned long long because count can exceed 2^24 and must
// be exact for the mean.
__device__ unsigned long long g_spike_count;

__global__ void zero_cnt_kernel() {
    g_spike_count = 0ull;
}

// Pass 1: out_spikes = (spikes >= 0.5f), and exact count of spikes.
// Vectorized float4 grid-stride loop; per-block reduction -> one atomicAdd.
__global__ void __launch_bounds__(256) spike_count_kernel(
    const float4* __restrict__ spikes4,
    float4* __restrict__ out_spikes4,
    int n4)
{
    unsigned int local = 0u;
    const int stride = gridDim.x * blockDim.x;
    for (int i = blockIdx.x * blockDim.x + threadIdx.x; i < n4; i += stride) {
        float4 v = __ldg(&spikes4[i]);
        float4 o;
        o.x = (v.x >= 0.5f) ? 1.0f : 0.0f;
        o.y = (v.y >= 0.5f) ? 1.0f : 0.0f;
        o.z = (v.z >= 0.5f) ? 1.0f : 0.0f;
        o.w = (v.w >= 0.5f) ? 1.0f : 0.0f;
        local += (unsigned)(v.x >= 0.5f) + (unsigned)(v.y >= 0.5f)
               + (unsigned)(v.z >= 0.5f) + (unsigned)(v.w >= 0.5f);
        out_spikes4[i] = o;
    }

    // Warp reduce
    #pragma unroll
    for (int off = 16; off > 0; off >>= 1)
        local += __shfl_down_sync(0xFFFFFFFFu, local, off);

    // Block reduce via smem
    __shared__ unsigned int warp_sums[8];  // 256 threads / 32
    const int lane = threadIdx.x & 31;
    const int wid  = threadIdx.x >> 5;
    if (lane == 0) warp_sums[wid] = local;
    __syncthreads();
    if (wid == 0) {
        unsigned int s = (lane < (blockDim.x >> 5)) ? warp_sums[lane] : 0u;
        #pragma unroll
        for (int off = 4; off > 0; off >>= 1)
            s += __shfl_down_sync(0xFFFFFFFFu, s, off);
        if (lane == 0)
            atomicAdd(&g_spike_count, (unsigned long long)s);
    }
}

// Pass 2: delta = S - P, where S = count / N (exact integer count -> double).
__global__ void __launch_bounds__(256) delta_kernel(
    const float4* __restrict__ P4,
    float4* __restrict__ delta4,
    int n4,
    double inv_n)
{
    const float S = (float)((double)g_spike_count * inv_n);
    const int stride = gridDim.x * blockDim.x;
    for (int i = blockIdx.x * blockDim.x + threadIdx.x; i < n4; i += stride) {
        float4 p = __ldg(&P4[i]);
        float4 d;
        d.x = S - p.x;
        d.y = S - p.y;
        d.z = S - p.z;
        d.w = S - p.w;
        delta4[i] = d;
    }
}

extern "C" void kernel_launch(void* const* d_in, const int* in_sizes, int n_in,
                              void* d_out, int out_size)
{
    const float* spikes = (const float*)d_in[0];
    const float* P      = (const float*)d_in[1];
    float* out          = (float*)d_out;

    const int n  = in_sizes[0];        // 33554432, divisible by 4
    const int n4 = n >> 2;

    float* delta_out  = out;           // first output: delta [n]
    float* spikes_out = out + n;       // second output: out_spikes [n]

    const int threads = 256;
    // Grid-stride with ~32 CTAs/SM worth of blocks keeps atomics cheap and
    // saturates HBM; cap at exact coverage for small n.
    int blocks = (n4 + threads - 1) / threads;
    const int max_blocks = 148 * 32;   // 4736
    if (blocks > max_blocks) blocks = max_blocks;

    zero_cnt_kernel<<<1, 1>>>();
    spike_count_kernel<<<blocks, threads>>>(
        (const float4*)spikes, (float4*)spikes_out, n4);
    delta_kernel<<<blocks, threads>>>(
        (const float4*)P, (float4*)delta_out, n4, 1.0 / (double)n);
}